// round 4
// baseline (speedup 1.0000x reference)
#include <cuda_runtime.h>
#include <cuda_bf16.h>
#include <math.h>

// ---------------------------------------------------------------------------
// Problem constants (all dims multiples of 128 -> no bounds checks anywhere)
// ---------------------------------------------------------------------------
#define BATCH 8
#define NSEQ  2048
#define HDIM  1024
#define FDIM  4096
#define MTOT  (BATCH * NSEQ)          // 16384 rows

// ---------------------------------------------------------------------------
// Scratch: __device__ globals (allocation-free per harness rules)
// ---------------------------------------------------------------------------
static __device__ float g_ln[(size_t)MTOT * HDIM];            // LN output (reused for LN1 and LN2)
static __device__ float g_q [(size_t)MTOT * HDIM];
static __device__ float g_k [(size_t)MTOT * HDIM];
static __device__ float g_v [(size_t)MTOT * HDIM];
static __device__ float g_x1[(size_t)MTOT * HDIM];            // x + attention (residual 1)
static __device__ float g_s [(size_t)BATCH * NSEQ * NSEQ];    // attention scores / probs
static __device__ float g_h [(size_t)MTOT * FDIM];            // FFN hidden

// ---------------------------------------------------------------------------
// Block reductions (256 threads)
// ---------------------------------------------------------------------------
__device__ __forceinline__ float block_reduce_max(float v) {
    __shared__ float sm[8];
    __syncthreads();  // safe reuse across consecutive calls
    #pragma unroll
    for (int o = 16; o; o >>= 1) v = fmaxf(v, __shfl_xor_sync(0xffffffffu, v, o));
    if ((threadIdx.x & 31) == 0) sm[threadIdx.x >> 5] = v;
    __syncthreads();
    if (threadIdx.x < 32) {
        float w = (threadIdx.x < 8) ? sm[threadIdx.x] : -INFINITY;
        #pragma unroll
        for (int o = 4; o; o >>= 1) w = fmaxf(w, __shfl_xor_sync(0xffffffffu, w, o));
        if (threadIdx.x == 0) sm[0] = w;
    }
    __syncthreads();
    return sm[0];
}

__device__ __forceinline__ float block_reduce_sum(float v) {
    __shared__ float sm[8];
    __syncthreads();
    #pragma unroll
    for (int o = 16; o; o >>= 1) v += __shfl_xor_sync(0xffffffffu, v, o);
    if ((threadIdx.x & 31) == 0) sm[threadIdx.x >> 5] = v;
    __syncthreads();
    if (threadIdx.x < 32) {
        float w = (threadIdx.x < 8) ? sm[threadIdx.x] : 0.0f;
        #pragma unroll
        for (int o = 4; o; o >>= 1) w += __shfl_xor_sync(0xffffffffu, w, o);
        if (threadIdx.x == 0) sm[0] = w;
    }
    __syncthreads();
    return sm[0];
}

// ---------------------------------------------------------------------------
// LayerNorm: 1 block per row of 1024 floats, 256 threads, float4 per thread
// ---------------------------------------------------------------------------
__global__ void __launch_bounds__(256) ln_kernel(
    const float* __restrict__ x, const float* __restrict__ g,
    const float* __restrict__ b, float* __restrict__ y)
{
    const size_t row = blockIdx.x;
    const float4 v = reinterpret_cast<const float4*>(x + row * HDIM)[threadIdx.x];
    float s  = v.x + v.y + v.z + v.w;
    float ss = v.x*v.x + v.y*v.y + v.z*v.z + v.w*v.w;

    __shared__ float sm_s[8], sm_ss[8];
    #pragma unroll
    for (int o = 16; o; o >>= 1) {
        s  += __shfl_xor_sync(0xffffffffu, s,  o);
        ss += __shfl_xor_sync(0xffffffffu, ss, o);
    }
    if ((threadIdx.x & 31) == 0) { sm_s[threadIdx.x >> 5] = s; sm_ss[threadIdx.x >> 5] = ss; }
    __syncthreads();
    if (threadIdx.x < 32) {
        float ws  = (threadIdx.x < 8) ? sm_s [threadIdx.x] : 0.0f;
        float wss = (threadIdx.x < 8) ? sm_ss[threadIdx.x] : 0.0f;
        #pragma unroll
        for (int o = 4; o; o >>= 1) {
            ws  += __shfl_xor_sync(0xffffffffu, ws,  o);
            wss += __shfl_xor_sync(0xffffffffu, wss, o);
        }
        if (threadIdx.x == 0) { sm_s[0] = ws; sm_ss[0] = wss; }
    }
    __syncthreads();

    const float mu  = sm_s[0]  * (1.0f / HDIM);
    const float var = sm_ss[0] * (1.0f / HDIM) - mu * mu;
    const float rs  = rsqrtf(var + 1e-5f);

    const float4 gv = reinterpret_cast<const float4*>(g)[threadIdx.x];
    const float4 bv = reinterpret_cast<const float4*>(b)[threadIdx.x];
    float4 o4;
    o4.x = (v.x - mu) * rs * gv.x + bv.x;
    o4.y = (v.y - mu) * rs * gv.y + bv.y;
    o4.z = (v.z - mu) * rs * gv.z + bv.z;
    o4.w = (v.w - mu) * rs * gv.w + bv.w;
    reinterpret_cast<float4*>(y + row * HDIM)[threadIdx.x] = o4;
}

// ---------------------------------------------------------------------------
// Softmax over rows of length 2048, in place. 1 block per row, 256 threads,
// 8 elements per thread held in registers between passes.
// ---------------------------------------------------------------------------
__global__ void __launch_bounds__(256) softmax_kernel(float* __restrict__ s)
{
    const size_t row = blockIdx.x;                          // 16384 rows
    float4* r = reinterpret_cast<float4*>(s) + row * (NSEQ / 4);
    const int t = threadIdx.x;
    float4 a = r[t];
    float4 c = r[t + 256];
    float vals[8] = {a.x, a.y, a.z, a.w, c.x, c.y, c.z, c.w};

    float m = vals[0];
    #pragma unroll
    for (int i = 1; i < 8; i++) m = fmaxf(m, vals[i]);
    m = block_reduce_max(m);

    float sum = 0.0f;
    #pragma unroll
    for (int i = 0; i < 8; i++) { vals[i] = expf(vals[i] - m); sum += vals[i]; }
    sum = block_reduce_sum(sum);

    const float inv = 1.0f / sum;
    a.x = vals[0]*inv; a.y = vals[1]*inv; a.z = vals[2]*inv; a.w = vals[3]*inv;
    c.x = vals[4]*inv; c.y = vals[5]*inv; c.z = vals[6]*inv; c.w = vals[7]*inv;
    r[t]       = a;
    r[t + 256] = c;
}

// ---------------------------------------------------------------------------
// SGEMM: C[M,N] = alpha * A[M,K] @ op(B) (+ epilogue)
//   TB=false : B is [K,N] row-major
//   TB=true  : B is [N,K] row-major (C = A @ B^T)
// Block tile 128x128, K-tile 8, 256 threads, 8x8 per-thread register tile.
// EPI: 0=none, 1=+res, 2=+bias then exact GELU, 3=+bias +res
// blockIdx.z batches with given element strides.
// ---------------------------------------------------------------------------
template<bool TB, int EPI>
__global__ void __launch_bounds__(256, 2) sgemm_kernel(
    const float* __restrict__ A, const float* __restrict__ B,
    float* __restrict__ C,
    int K, int lda, int ldb, int ldc,
    long long strA, long long strB, long long strC,
    float alpha,
    const float* __restrict__ bias,
    const float* __restrict__ res, long long strRes)
{
    __shared__ __align__(16) float As[8][132];
    __shared__ __align__(16) float Bs[8][132];

    const int bz = blockIdx.z;
    A += strA * bz;
    B += strB * bz;
    C += strC * bz;

    const int bm = blockIdx.y * 128;
    const int bn = blockIdx.x * 128;
    const int tid = threadIdx.x;
    const int tx = tid & 15;          // 16 col-threads
    const int ty = tid >> 4;          // 16 row-threads

    const int lrow = tid >> 1;        // 0..127 (A / NT-B loader row)
    const int lk4  = (tid & 1) * 4;   // 0 or 4
    const int bk   = tid >> 5;        // 0..7   (NN-B loader k)
    const int bn4  = (tid & 31) * 4;  // 0..124

    const float* Aptr = A + (size_t)(bm + lrow) * lda + lk4;
    const float* Bptr = TB ? (B + (size_t)(bn + lrow) * ldb + lk4)
                           : (B + (size_t)bk * ldb + bn + bn4);

    float acc[8][8];
    #pragma unroll
    for (int i = 0; i < 8; i++)
        #pragma unroll
        for (int j = 0; j < 8; j++) acc[i][j] = 0.0f;

    for (int k0 = 0; k0 < K; k0 += 8) {
        const float4 av = *reinterpret_cast<const float4*>(Aptr);
        Aptr += 8;
        float4 bv;
        if (TB) { bv = *reinterpret_cast<const float4*>(Bptr); Bptr += 8; }
        else    { bv = *reinterpret_cast<const float4*>(Bptr); Bptr += (size_t)8 * ldb; }

        __syncthreads();
        As[lk4+0][lrow] = av.x; As[lk4+1][lrow] = av.y;
        As[lk4+2][lrow] = av.z; As[lk4+3][lrow] = av.w;
        if (TB) {
            Bs[lk4+0][lrow] = bv.x; Bs[lk4+1][lrow] = bv.y;
            Bs[lk4+2][lrow] = bv.z; Bs[lk4+3][lrow] = bv.w;
        } else {
            *reinterpret_cast<float4*>(&Bs[bk][bn4]) = bv;
        }
        __syncthreads();

        #pragma unroll
        for (int kk = 0; kk < 8; kk++) {
            const float4 a0 = *reinterpret_cast<const float4*>(&As[kk][ty * 8]);
            const float4 a1 = *reinterpret_cast<const float4*>(&As[kk][ty * 8 + 4]);
            const float4 b0 = *reinterpret_cast<const float4*>(&Bs[kk][tx * 8]);
            const float4 b1 = *reinterpret_cast<const float4*>(&Bs[kk][tx * 8 + 4]);
            const float ar[8] = {a0.x, a0.y, a0.z, a0.w, a1.x, a1.y, a1.z, a1.w};
            const float br[8] = {b0.x, b0.y, b0.z, b0.w, b1.x, b1.y, b1.z, b1.w};
            #pragma unroll
            for (int i = 0; i < 8; i++)
                #pragma unroll
                for (int j = 0; j < 8; j++)
                    acc[i][j] = fmaf(ar[i], br[j], acc[i][j]);
        }
    }

    // Epilogue
    #pragma unroll
    for (int i = 0; i < 8; i++) {
        const int row = bm + ty * 8 + i;
        float* crow = C + (size_t)row * ldc + bn + tx * 8;
        const float* rrow = nullptr;
        if constexpr (EPI == 1 || EPI == 3)
            rrow = res + strRes * blockIdx.z + (size_t)row * ldc + bn + tx * 8;

        #pragma unroll
        for (int j = 0; j < 8; j += 4) {
            float4 o;
            o.x = acc[i][j + 0] * alpha;
            o.y = acc[i][j + 1] * alpha;
            o.z = acc[i][j + 2] * alpha;
            o.w = acc[i][j + 3] * alpha;
            if constexpr (EPI == 2 || EPI == 3) {
                const float4 bb = *reinterpret_cast<const float4*>(&bias[bn + tx * 8 + j]);
                o.x += bb.x; o.y += bb.y; o.z += bb.z; o.w += bb.w;
            }
            if constexpr (EPI == 2) {  // exact GELU: 0.5*x*(1+erf(x/sqrt(2)))
                o.x = 0.5f * o.x * (1.0f + erff(o.x * 0.70710678118654752f));
                o.y = 0.5f * o.y * (1.0f + erff(o.y * 0.70710678118654752f));
                o.z = 0.5f * o.z * (1.0f + erff(o.z * 0.70710678118654752f));
                o.w = 0.5f * o.w * (1.0f + erff(o.w * 0.70710678118654752f));
            }
            if constexpr (EPI == 1 || EPI == 3) {
                const float4 rr = *reinterpret_cast<const float4*>(&rrow[j]);
                o.x += rr.x; o.y += rr.y; o.z += rr.z; o.w += rr.w;
            }
            *reinterpret_cast<float4*>(&crow[j]) = o;
        }
    }
}

// ---------------------------------------------------------------------------
// kernel_launch — inputs per metadata order:
// 0:x 1:ln1_g 2:ln1_b 3:Wq 4:Wk 5:Wv 6:ln2_g 7:ln2_b 8:W1 9:b1 10:W2 11:b2
// ---------------------------------------------------------------------------
extern "C" void kernel_launch(void* const* d_in, const int* /*in_sizes*/, int /*n_in*/,
                              void* d_out, int /*out_size*/)
{
    const float* x     = (const float*)d_in[0];
    const float* ln1_g = (const float*)d_in[1];
    const float* ln1_b = (const float*)d_in[2];
    const float* Wq    = (const float*)d_in[3];
    const float* Wk    = (const float*)d_in[4];
    const float* Wv    = (const float*)d_in[5];
    const float* ln2_g = (const float*)d_in[6];
    const float* ln2_b = (const float*)d_in[7];
    const float* W1    = (const float*)d_in[8];
    const float* b1    = (const float*)d_in[9];
    const float* W2    = (const float*)d_in[10];
    const float* b2    = (const float*)d_in[11];
    float* out = (float*)d_out;

    float *ln, *q, *k, *v, *x1, *s, *h;
    cudaGetSymbolAddress((void**)&ln, g_ln);
    cudaGetSymbolAddress((void**)&q,  g_q);
    cudaGetSymbolAddress((void**)&k,  g_k);
    cudaGetSymbolAddress((void**)&v,  g_v);
    cudaGetSymbolAddress((void**)&x1, g_x1);
    cudaGetSymbolAddress((void**)&s,  g_s);
    cudaGetSymbolAddress((void**)&h,  g_h);

    const long long sNH = (long long)NSEQ * HDIM;   // 2048*1024
    const long long sNN = (long long)NSEQ * NSEQ;   // 2048*2048

    // 1) LN1
    ln_kernel<<<MTOT, 256>>>(x, ln1_g, ln1_b, ln);

    // 2) Q,K,V = ln @ W  (M=16384, N=1024, K=1024)
    {
        dim3 grid(HDIM / 128, MTOT / 128);
        sgemm_kernel<false, 0><<<grid, 256>>>(ln, Wq, q, HDIM, HDIM, HDIM, HDIM,
                                              0, 0, 0, 1.0f, nullptr, nullptr, 0);
        sgemm_kernel<false, 0><<<grid, 256>>>(ln, Wk, k, HDIM, HDIM, HDIM, HDIM,
                                              0, 0, 0, 1.0f, nullptr, nullptr, 0);
        sgemm_kernel<false, 0><<<grid, 256>>>(ln, Wv, v, HDIM, HDIM, HDIM, HDIM,
                                              0, 0, 0, 1.0f, nullptr, nullptr, 0);
    }

    // 3) scores = (Q @ K^T) / 32, batched over 8
    {
        dim3 grid(NSEQ / 128, NSEQ / 128, BATCH);
        sgemm_kernel<true, 0><<<grid, 256>>>(q, k, s, HDIM, HDIM, HDIM, NSEQ,
                                             sNH, sNH, sNN, 0.03125f,
                                             nullptr, nullptr, 0);
    }

    // 4) softmax over last dim (in place)
    softmax_kernel<<<BATCH * NSEQ, 256>>>(s);

    // 5) x1 = x + att @ V, batched
    {
        dim3 grid(HDIM / 128, NSEQ / 128, BATCH);
        sgemm_kernel<false, 1><<<grid, 256>>>(s, v, x1, NSEQ, NSEQ, HDIM, HDIM,
                                              sNN, sNH, sNH, 1.0f,
                                              nullptr, x, sNH);
    }

    // 6) LN2
    ln_kernel<<<MTOT, 256>>>(x1, ln2_g, ln2_b, ln);

    // 7) h = gelu(ln @ W1 + b1)   (M=16384, N=4096, K=1024)
    {
        dim3 grid(FDIM / 128, MTOT / 128);
        sgemm_kernel<false, 2><<<grid, 256>>>(ln, W1, h, HDIM, HDIM, FDIM, FDIM,
                                              0, 0, 0, 1.0f, b1, nullptr, 0);
    }

    // 8) out = x1 + h @ W2 + b2   (M=16384, N=1024, K=4096)
    {
        dim3 grid(HDIM / 128, MTOT / 128);
        sgemm_kernel<false, 3><<<grid, 256>>>(h, W2, out, FDIM, FDIM, HDIM, HDIM,
                                              0, 0, 0, 1.0f, b2, x1, 0);
    }
}